// round 16
// baseline (speedup 1.0000x reference)
#include <cuda_runtime.h>
#include <cstdint>

#define NN 100000
#define NP 100096              // 782 * 128 padded rows
#define DD 128
#define EE 1600000
#define ND (NN * DD)
#define MBLK 782

// ---------------- scratch (padded to NP rows; device globals zero-init) ----------------
__device__ float g_h[NP * DD];
__device__ float g_agg[NP * DD];
__device__ float g_gi[NP * 384];
__device__ float g_M[3 * 384 * 128];   // M_l[j][t] = sum_k W_ih[j,k] * W_l[t,k]
__device__ int   g_src[EE];
__device__ int   g_dst[EE];
__device__ int   g_esrc[EE];
__device__ float g_ew[EE];
__device__ int   g_deg[NN];
__device__ int   g_eoff[NN + 1];
__device__ int   g_epos[NN];
__device__ int   g_is64;

// ---------------- f32x2 helpers ----------------
__device__ __forceinline__ unsigned long long pack2(float x, float y) {
    unsigned long long r;
    asm("mov.b64 %0, {%1, %2};" : "=l"(r) : "f"(x), "f"(y));
    return r;
}
__device__ __forceinline__ void fma2(unsigned long long& d, unsigned long long a, unsigned long long b) {
    asm("fma.rn.f32x2 %0, %1, %2, %0;" : "+l"(d) : "l"(a), "l"(b));
}
__device__ __forceinline__ float2 unpack2(unsigned long long v) {
    float2 f;
    asm("mov.b64 {%0, %1}, %2;" : "=f"(f.x), "=f"(f.y) : "l"(v));
    return f;
}
__device__ __forceinline__ float sigm(float x) { return 1.f / (1.f + expf(-x)); }

// ---------------- utility kernels ----------------
__global__ void copy4_kernel(float4* __restrict__ dst, const float4* __restrict__ src, int n4) {
    int i = blockIdx.x * blockDim.x + threadIdx.x;
    if (i < n4) dst[i] = src[i];
}
__global__ void detect_kernel(const unsigned int* __restrict__ p) {
    if (blockIdx.x == 0 && threadIdx.x == 0) {
        unsigned long long s = 0;
        for (int i = 1; i < 2048; i += 2) s += p[i];
        g_is64 = (s == 0ull) ? 1 : 0;
    }
}
__global__ void conv_edges_kernel(const int* __restrict__ p) {
    int i = blockIdx.x * blockDim.x + threadIdx.x;
    if (i >= EE) return;
    if (g_is64) { g_src[i] = p[2 * i]; g_dst[i] = p[2 * (EE + i)]; }
    else        { g_src[i] = p[i];     g_dst[i] = p[EE + i]; }
}

// ---------------- CSR build ----------------
__global__ void zero_deg_kernel() {
    int i = blockIdx.x * blockDim.x + threadIdx.x;
    if (i < NN) g_deg[i] = 0;
}
__global__ void hist_kernel() {
    int i = blockIdx.x * blockDim.x + threadIdx.x;
    if (i < EE) atomicAdd(&g_deg[g_dst[i]], 1);
}
__global__ void scan_kernel() {
    __shared__ int ssum[256];
    int t = threadIdx.x;
    int b = t * 392;
    int e = min(b + 392, NN);
    int s = 0;
    for (int n = b; n < e; n++) s += g_deg[n];
    ssum[t] = s;
    __syncthreads();
    if (t == 0) {
        int run = 0;
        for (int i = 0; i < 256; i++) { int v = ssum[i]; ssum[i] = run; run += v; }
    }
    __syncthreads();
    int run = ssum[t];
    for (int n = b; n < e; n++) {
        g_eoff[n] = run;
        g_epos[n] = run;
        run += g_deg[n];
    }
    if (t == 255) g_eoff[NN] = run;
}
__global__ void fill_kernel(const float* __restrict__ ea) {
    int i = blockIdx.x * blockDim.x + threadIdx.x;
    if (i >= EE) return;
    int d = g_dst[i];
    int slot = atomicAdd(&g_epos[d], 1);
    g_esrc[slot] = g_src[i];
    g_ew[slot] = ea[i];
}

// ---------------- M_l = W_ih @ W_l^T ----------------
__global__ void mcomb_kernel(const float* __restrict__ W, const float* __restrict__ W_ih) {
    int idx = blockIdx.x * blockDim.x + threadIdx.x;
    if (idx >= 384 * 128) return;
    int l = blockIdx.y;
    int j = idx >> 7, t = idx & 127;
    const float* wi = W_ih + j * 128;
    const float* wl = W + l * 128 * 128 + t * 128;
    float s = 0.f;
#pragma unroll 8
    for (int k = 0; k < 128; k++) s = fmaf(__ldg(&wi[k]), __ldg(&wl[k]), s);
    g_M[(l * 384 + j) * 128 + t] = s;
}

// ---------------- gather: agg[n] = sum_{e: dst=n} h[src_e] * w_e (warp per node) ----------------
__global__ void gather_kernel() {
    int gw = (blockIdx.x * blockDim.x + threadIdx.x) >> 5;
    int lane = threadIdx.x & 31;
    if (gw >= NN) return;
    int beg = g_eoff[gw], end = g_eoff[gw + 1];
    float4 acc = make_float4(0.f, 0.f, 0.f, 0.f);
    for (int e = beg; e < end; e++) {
        int s = __ldg(&g_esrc[e]);
        float w = __ldg(&g_ew[e]);
        float4 v = *((const float4*)g_h + (size_t)s * 32 + lane);
        acc.x = fmaf(v.x, w, acc.x);
        acc.y = fmaf(v.y, w, acc.y);
        acc.z = fmaf(v.z, w, acc.z);
        acc.w = fmaf(v.w, w, acc.w);
    }
    *((float4*)g_agg + (size_t)gw * 32 + lane) = acc;
}

// ---------------- one K=128 GEMM pass (128x128 tile, R13-proven geometry) ----------------
__device__ __forceinline__ void gemm_pass(float* As, unsigned long long* Bsd,
                                          unsigned long long acc[8][4],
                                          const float* __restrict__ Arow,
                                          const float* __restrict__ Brow,
                                          int lm, int l0, int tx, int ty) {
    float4 a0 = *(const float4*)&Arow[l0];
    float4 a1 = *(const float4*)&Arow[l0 + 4];
    float4 b0 = *(const float4*)&Brow[l0];
    float4 b1 = *(const float4*)&Brow[l0 + 4];

    for (int c = 0; c < 8; c++) {
        __syncthreads();
        As[(l0 + 0) * 132 + lm] = a0.x; As[(l0 + 1) * 132 + lm] = a0.y;
        As[(l0 + 2) * 132 + lm] = a0.z; As[(l0 + 3) * 132 + lm] = a0.w;
        As[(l0 + 4) * 132 + lm] = a1.x; As[(l0 + 5) * 132 + lm] = a1.y;
        As[(l0 + 6) * 132 + lm] = a1.z; As[(l0 + 7) * 132 + lm] = a1.w;
        Bsd[(l0 + 0) * 132 + lm] = pack2(b0.x, b0.x); Bsd[(l0 + 1) * 132 + lm] = pack2(b0.y, b0.y);
        Bsd[(l0 + 2) * 132 + lm] = pack2(b0.z, b0.z); Bsd[(l0 + 3) * 132 + lm] = pack2(b0.w, b0.w);
        Bsd[(l0 + 4) * 132 + lm] = pack2(b1.x, b1.x); Bsd[(l0 + 5) * 132 + lm] = pack2(b1.y, b1.y);
        Bsd[(l0 + 6) * 132 + lm] = pack2(b1.z, b1.z); Bsd[(l0 + 7) * 132 + lm] = pack2(b1.w, b1.w);
        __syncthreads();

        if (c < 7) {
            int kn = (c + 1) * 16;
            a0 = *(const float4*)&Arow[kn + l0];
            a1 = *(const float4*)&Arow[kn + l0 + 4];
            b0 = *(const float4*)&Brow[kn + l0];
            b1 = *(const float4*)&Brow[kn + l0 + 4];
        }

#pragma unroll
        for (int kk = 0; kk < 16; kk++) {
            ulonglong2 pa0 = *(const ulonglong2*)&As[kk * 132 + ty * 8];
            ulonglong2 pa1 = *(const ulonglong2*)&As[kk * 132 + ty * 8 + 4];
            unsigned long long ap0 = pa0.x, ap1 = pa0.y, ap2 = pa1.x, ap3 = pa1.y;
#pragma unroll
            for (int jj = 0; jj < 8; jj++) {
                unsigned long long b2 = Bsd[kk * 132 + tx + 16 * jj];
                fma2(acc[jj][0], ap0, b2);
                fma2(acc[jj][1], ap1, b2);
                fma2(acc[jj][2], ap2, b2);
                fma2(acc[jj][3], ap3, b2);
            }
        }
    }
}

// ---------------- gi = agg @ M_l^T + b_ih   (grid: MBLK x 3, R13 geometry) ----------------
#define SMEM_GI 25344
__global__ __launch_bounds__(256) void gi_kernel(const float* __restrict__ Ml,
                                                 const float* __restrict__ b_ih) {
    extern __shared__ char smem[];
    float* As = (float*)smem;
    unsigned long long* Bsd = (unsigned long long*)(smem + 8448);

    const int tid = threadIdx.x;
    const int tx = tid & 15, ty = tid >> 4;
    const int lm = tid >> 1;
    const int l0 = ((tid * 2) & 3) * 4;
    const int m0 = blockIdx.x * 128;
    const int j0 = blockIdx.y * 128;

    unsigned long long acc[8][4];
#pragma unroll
    for (int jj = 0; jj < 8; jj++) {
        float bj = __ldg(&b_ih[j0 + tx + 16 * jj]);
        unsigned long long b2 = pack2(bj, bj);
#pragma unroll
        for (int p = 0; p < 4; p++) acc[jj][p] = b2;
    }

    gemm_pass(As, Bsd, acc,
              g_agg + (size_t)(m0 + lm) * 128,
              Ml + (size_t)(j0 + lm) * 128, lm, l0, tx, ty);

#pragma unroll
    for (int jj = 0; jj < 8; jj++) {
        int col = j0 + tx + 16 * jj;
#pragma unroll
        for (int p = 0; p < 4; p++) {
            float2 v = unpack2(acc[jj][p]);
            int r0 = m0 + ty * 8 + 2 * p;
            g_gi[(size_t)r0 * 384 + col] = v.x;
            g_gi[(size_t)(r0 + 1) * 384 + col] = v.y;
        }
    }
}

// ---------------- fused gh + GRU: 3 passes (r, n, z) per CTA, R13 tile geometry ----------------
// SMEM: As 8448 + Bsd 16896 + stage [64][256] f32 65536 = 90880  => 2 CTAs/SM
#define SMEM_GH (25344 + 65536)

__global__ __launch_bounds__(256) void ghgru_kernel(const float* __restrict__ W_hh,
                                                    const float* __restrict__ b_hh,
                                                    float* __restrict__ hout) {
    extern __shared__ char smem[];
    float* As = (float*)smem;
    unsigned long long* Bsd = (unsigned long long*)(smem + 8448);
    float* stg = (float*)(smem + 25344);   // [e][tid], thread-private slots

    const int tid = threadIdx.x;
    const int tx = tid & 15, ty = tid >> 4;
    const int lm = tid >> 1;
    const int l0 = ((tid * 2) & 3) * 4;
    const int m0 = blockIdx.x * 128;
    const float* HRow = g_h + (size_t)(m0 + lm) * 128;

    unsigned long long acc[8][4];
    const int goff[3] = {0, 256, 128};     // pass order: r, n, z

    for (int ps = 0; ps < 3; ps++) {
        int go = goff[ps];
#pragma unroll
        for (int jj = 0; jj < 8; jj++) {
            float bj = __ldg(&b_hh[go + tx + 16 * jj]);
            unsigned long long b2 = pack2(bj, bj);
#pragma unroll
            for (int p = 0; p < 4; p++) acc[jj][p] = b2;
        }

        gemm_pass(As, Bsd, acc, HRow, W_hh + (size_t)(go + lm) * 128, lm, l0, tx, ty);

        if (ps == 0) {
            // r = sigmoid(gi_r + acc) -> stage
#pragma unroll
            for (int jj = 0; jj < 8; jj++) {
                int col = tx + 16 * jj;
#pragma unroll
                for (int p = 0; p < 4; p++) {
                    float2 v = unpack2(acc[jj][p]);
                    int r0 = m0 + ty * 8 + 2 * p;
                    int e = jj * 8 + p * 2;
                    stg[e * 256 + tid] = sigm(__ldg(&g_gi[(size_t)r0 * 384 + col]) + v.x);
                    stg[(e + 1) * 256 + tid] = sigm(__ldg(&g_gi[(size_t)(r0 + 1) * 384 + col]) + v.y);
                }
            }
        } else if (ps == 1) {
            // n = tanh(gi_n + r * acc) -> stage (overwrite r)
#pragma unroll
            for (int jj = 0; jj < 8; jj++) {
                int col = 256 + tx + 16 * jj;
#pragma unroll
                for (int p = 0; p < 4; p++) {
                    float2 v = unpack2(acc[jj][p]);
                    int r0 = m0 + ty * 8 + 2 * p;
                    int e = jj * 8 + p * 2;
                    float ra = stg[e * 256 + tid], rb = stg[(e + 1) * 256 + tid];
                    stg[e * 256 + tid] = tanhf(__ldg(&g_gi[(size_t)r0 * 384 + col]) + ra * v.x);
                    stg[(e + 1) * 256 + tid] = tanhf(__ldg(&g_gi[(size_t)(r0 + 1) * 384 + col]) + rb * v.y);
                }
            }
        } else {
            // z = sigmoid(gi_z + acc); h_new = (1-z)*n + z*h  (in-place safe: own rows only)
#pragma unroll
            for (int jj = 0; jj < 8; jj++) {
                int colz = 128 + tx + 16 * jj;
                int col = tx + 16 * jj;
#pragma unroll
                for (int p = 0; p < 4; p++) {
                    float2 v = unpack2(acc[jj][p]);
                    int r0 = m0 + ty * 8 + 2 * p;
                    int e = jj * 8 + p * 2;
#pragma unroll
                    for (int q = 0; q < 2; q++) {
                        int row = r0 + q;
                        if (row < NN) {
                            float z = sigm(__ldg(&g_gi[(size_t)row * 384 + colz]) + (q ? v.y : v.x));
                            float n = stg[(e + q) * 256 + tid];
                            float hv = g_h[(size_t)row * 128 + col];
                            hout[(size_t)row * 128 + col] = (1.f - z) * n + z * hv;
                        }
                    }
                }
            }
        }
    }
}

// ---------------- launch ----------------
extern "C" void kernel_launch(void* const* d_in, const int* in_sizes, int n_in,
                              void* d_out, int out_size) {
    const float* x    = (const float*)d_in[0];
    const int*   ei   = (const int*)d_in[1];
    const float* ea   = (const float*)d_in[2];
    const float* W    = (const float*)d_in[3];
    const float* W_ih = (const float*)d_in[4];
    const float* W_hh = (const float*)d_in[5];
    const float* b_ih = (const float*)d_in[6];
    const float* b_hh = (const float*)d_in[7];
    float* out = (float*)d_out;

    cudaFuncSetAttribute(gi_kernel,    cudaFuncAttributeMaxDynamicSharedMemorySize, SMEM_GI);
    cudaFuncSetAttribute(ghgru_kernel, cudaFuncAttributeMaxDynamicSharedMemorySize, SMEM_GH);

    float *ph, *pM;
    cudaGetSymbolAddress((void**)&ph, g_h);
    cudaGetSymbolAddress((void**)&pM, g_M);

    const int n4 = ND / 4;

    detect_kernel<<<1, 32>>>((const unsigned int*)ei);
    conv_edges_kernel<<<EE / 256, 256>>>(ei);
    copy4_kernel<<<n4 / 256, 256>>>((float4*)ph, (const float4*)x, n4);

    zero_deg_kernel<<<(NN + 255) / 256, 256>>>();
    hist_kernel<<<EE / 256, 256>>>();
    scan_kernel<<<1, 256>>>();
    fill_kernel<<<EE / 256, 256>>>(ea);

    mcomb_kernel<<<dim3(192, 3), 256>>>(W, W_ih);

    for (int l = 0; l < 3; l++) {
        gather_kernel<<<(NN * 32 + 255) / 256, 256>>>();
        gi_kernel<<<dim3(MBLK, 3), 256, SMEM_GI>>>(pM + (size_t)l * 384 * 128, b_ih);
        float* hout = (l == 2) ? out : ph;
        ghgru_kernel<<<MBLK, 256, SMEM_GH>>>(W_hh, b_hh, hout);
    }
}

// round 17
// speedup vs baseline: 1.4996x; 1.4996x over previous
#include <cuda_runtime.h>
#include <cstdint>

#define NN 100000
#define DD 128
#define EE 1600000
#define ND (NN * DD)
#define MBLK 782

// ---------------- scratch ----------------
__device__ float g_h[ND];
__device__ float g_agg[ND];
__device__ float g_gi[NN * 384];
__device__ float g_gh[NN * 384];
__device__ float g_M[3 * 384 * 128];   // M_l[j][t] = sum_k W_ih[j,k] * W_l[t,k]
__device__ int   g_src[EE];
__device__ int   g_dst[EE];
__device__ int   g_esrc[EE];
__device__ float g_ew[EE];
__device__ int   g_deg[NN];
__device__ int   g_eoff[NN + 1];
__device__ int   g_epos[NN];
__device__ int   g_is64;

// ---------------- f32x2 helpers ----------------
__device__ __forceinline__ unsigned long long pack2(float x, float y) {
    unsigned long long r;
    asm("mov.b64 %0, {%1, %2};" : "=l"(r) : "f"(x), "f"(y));
    return r;
}
__device__ __forceinline__ void fma2(unsigned long long& d, unsigned long long a, unsigned long long b) {
    asm("fma.rn.f32x2 %0, %1, %2, %0;" : "+l"(d) : "l"(a), "l"(b));
}
__device__ __forceinline__ float2 unpack2(unsigned long long v) {
    float2 f;
    asm("mov.b64 {%0, %1}, %2;" : "=f"(f.x), "=f"(f.y) : "l"(v));
    return f;
}
__device__ __forceinline__ float sigm(float x) { return 1.f / (1.f + expf(-x)); }

// ---------------- utility kernels ----------------
__global__ void copy4_kernel(float4* __restrict__ dst, const float4* __restrict__ src, int n4) {
    int i = blockIdx.x * blockDim.x + threadIdx.x;
    if (i < n4) dst[i] = src[i];
}
__global__ void detect_kernel(const unsigned int* __restrict__ p) {
    if (blockIdx.x == 0 && threadIdx.x == 0) {
        unsigned long long s = 0;
        for (int i = 1; i < 2048; i += 2) s += p[i];
        g_is64 = (s == 0ull) ? 1 : 0;
    }
}
__global__ void conv_edges_kernel(const int* __restrict__ p) {
    int i = blockIdx.x * blockDim.x + threadIdx.x;
    if (i >= EE) return;
    if (g_is64) { g_src[i] = p[2 * i]; g_dst[i] = p[2 * (EE + i)]; }
    else        { g_src[i] = p[i];     g_dst[i] = p[EE + i]; }
}

// ---------------- CSR build ----------------
__global__ void zero_deg_kernel() {
    int i = blockIdx.x * blockDim.x + threadIdx.x;
    if (i < NN) g_deg[i] = 0;
}
__global__ void hist_kernel() {
    int i = blockIdx.x * blockDim.x + threadIdx.x;
    if (i < EE) atomicAdd(&g_deg[g_dst[i]], 1);
}
__global__ void scan_kernel() {
    __shared__ int ssum[256];
    int t = threadIdx.x;
    int b = t * 392;
    int e = min(b + 392, NN);
    int s = 0;
    for (int n = b; n < e; n++) s += g_deg[n];
    ssum[t] = s;
    __syncthreads();
    if (t == 0) {
        int run = 0;
        for (int i = 0; i < 256; i++) { int v = ssum[i]; ssum[i] = run; run += v; }
    }
    __syncthreads();
    int run = ssum[t];
    for (int n = b; n < e; n++) {
        g_eoff[n] = run;
        g_epos[n] = run;
        run += g_deg[n];
    }
    if (t == 255) g_eoff[NN] = run;
}
__global__ void fill_kernel(const float* __restrict__ ea) {
    int i = blockIdx.x * blockDim.x + threadIdx.x;
    if (i >= EE) return;
    int d = g_dst[i];
    int slot = atomicAdd(&g_epos[d], 1);
    g_esrc[slot] = g_src[i];
    g_ew[slot] = ea[i];
}

// ---------------- M_l = W_ih @ W_l^T ----------------
__global__ void mcomb_kernel(const float* __restrict__ W, const float* __restrict__ W_ih) {
    int idx = blockIdx.x * blockDim.x + threadIdx.x;
    if (idx >= 384 * 128) return;
    int l = blockIdx.y;
    int j = idx >> 7, t = idx & 127;
    const float* wi = W_ih + j * 128;
    const float* wl = W + l * 128 * 128 + t * 128;
    float s = 0.f;
#pragma unroll 8
    for (int k = 0; k < 128; k++) s = fmaf(__ldg(&wi[k]), __ldg(&wl[k]), s);
    g_M[(l * 384 + j) * 128 + t] = s;
}

// ---------------- gather: agg[n] = sum_{e: dst=n} h[src_e] * w_e (warp per node) ----------------
__global__ void gather_kernel() {
    int gw = (blockIdx.x * blockDim.x + threadIdx.x) >> 5;
    int lane = threadIdx.x & 31;
    if (gw >= NN) return;
    int beg = g_eoff[gw], end = g_eoff[gw + 1];
    float4 acc = make_float4(0.f, 0.f, 0.f, 0.f);
    for (int e = beg; e < end; e++) {
        int s = __ldg(&g_esrc[e]);
        float w = __ldg(&g_ew[e]);
        float4 v = *((const float4*)g_h + (size_t)s * 32 + lane);
        acc.x = fmaf(v.x, w, acc.x);
        acc.y = fmaf(v.y, w, acc.y);
        acc.z = fmaf(v.z, w, acc.z);
        acc.w = fmaf(v.w, w, acc.w);
    }
    *((float4*)g_agg + (size_t)gw * 32 + lane) = acc;
}

// ---------------- GEMM (R13-proven, unchanged): C = A @ Bt^T + bias ----------------
__launch_bounds__(256)
__global__ void gemm_bt_kernel(const float* __restrict__ A, const float* __restrict__ Bt,
                               const float* __restrict__ bias, float* __restrict__ C,
                               int M, int ldc) {
    __shared__ float As[16][132];
    __shared__ unsigned long long Bsd[16][132];

    const int m0  = blockIdx.x * 128;
    const int j0  = blockIdx.y * 128;
    const int tid = threadIdx.x;
    const int tx  = tid & 15;
    const int ty  = tid >> 4;

    const int lm = tid >> 1;
    const int l0 = ((tid * 2) & 3) * 4;

    unsigned long long acc[8][4];
#pragma unroll
    for (int jj = 0; jj < 8; jj++) {
        float bj = bias ? __ldg(&bias[j0 + tx + 16 * jj]) : 0.f;
        unsigned long long b2 = pack2(bj, bj);
#pragma unroll
        for (int p = 0; p < 4; p++) acc[jj][p] = b2;
    }

    const bool arow_ok = (m0 + lm) < M;
    const float* Arow = A + (size_t)(m0 + lm) * 128;
    const float* Brow = Bt + (size_t)(j0 + lm) * 128;
    const float4 zf4 = make_float4(0.f, 0.f, 0.f, 0.f);

    float4 a0 = arow_ok ? *(const float4*)&Arow[l0]     : zf4;
    float4 a1 = arow_ok ? *(const float4*)&Arow[l0 + 4] : zf4;
    float4 b0 = *(const float4*)&Brow[l0];
    float4 b1 = *(const float4*)&Brow[l0 + 4];

    for (int c = 0; c < 8; c++) {
        __syncthreads();
        As[l0 + 0][lm] = a0.x; As[l0 + 1][lm] = a0.y; As[l0 + 2][lm] = a0.z; As[l0 + 3][lm] = a0.w;
        As[l0 + 4][lm] = a1.x; As[l0 + 5][lm] = a1.y; As[l0 + 6][lm] = a1.z; As[l0 + 7][lm] = a1.w;
        Bsd[l0 + 0][lm] = pack2(b0.x, b0.x); Bsd[l0 + 1][lm] = pack2(b0.y, b0.y);
        Bsd[l0 + 2][lm] = pack2(b0.z, b0.z); Bsd[l0 + 3][lm] = pack2(b0.w, b0.w);
        Bsd[l0 + 4][lm] = pack2(b1.x, b1.x); Bsd[l0 + 5][lm] = pack2(b1.y, b1.y);
        Bsd[l0 + 6][lm] = pack2(b1.z, b1.z); Bsd[l0 + 7][lm] = pack2(b1.w, b1.w);
        __syncthreads();

        if (c < 7) {
            int kn = (c + 1) * 16;
            a0 = arow_ok ? *(const float4*)&Arow[kn + l0]     : zf4;
            a1 = arow_ok ? *(const float4*)&Arow[kn + l0 + 4] : zf4;
            b0 = *(const float4*)&Brow[kn + l0];
            b1 = *(const float4*)&Brow[kn + l0 + 4];
        }

#pragma unroll
        for (int kk = 0; kk < 16; kk++) {
            ulonglong2 pa0 = *(const ulonglong2*)&As[kk][ty * 8];
            ulonglong2 pa1 = *(const ulonglong2*)&As[kk][ty * 8 + 4];
            unsigned long long ap0 = pa0.x, ap1 = pa0.y, ap2 = pa1.x, ap3 = pa1.y;
#pragma unroll
            for (int jj = 0; jj < 8; jj++) {
                unsigned long long b2 = Bsd[kk][tx + 16 * jj];
                fma2(acc[jj][0], ap0, b2);
                fma2(acc[jj][1], ap1, b2);
                fma2(acc[jj][2], ap2, b2);
                fma2(acc[jj][3], ap3, b2);
            }
        }
    }

#pragma unroll
    for (int jj = 0; jj < 8; jj++) {
        int col = j0 + tx + 16 * jj;
#pragma unroll
        for (int p = 0; p < 4; p++) {
            float2 v = unpack2(acc[jj][p]);
            int r0 = m0 + ty * 8 + 2 * p;
            if (r0 < M)     C[(size_t)r0 * ldc + col]       = v.x;
            if (r0 + 1 < M) C[(size_t)(r0 + 1) * ldc + col] = v.y;
        }
    }
}

// ---------------- GRU gate elementwise (float4; writes hout) ----------------
__global__ void gru_kernel(float* __restrict__ hout) {
    int i = blockIdx.x * blockDim.x + threadIdx.x;   // over ND/4
    if (i >= ND / 4) return;
    int n = i >> 5, c4 = i & 31;
    const float4* gi4 = (const float4*)g_gi + (size_t)n * 96 + c4;
    const float4* gh4 = (const float4*)g_gh + (size_t)n * 96 + c4;
    float4 ir = gi4[0], iz = gi4[32], in_ = gi4[64];
    float4 hr = gh4[0], hz = gh4[32], hn = gh4[64];
    float4 hv = *((const float4*)g_h + i);
    float4 o;
    {
        float r = sigm(ir.x + hr.x), z = sigm(iz.x + hz.x);
        o.x = (1.f - z) * tanhf(in_.x + r * hn.x) + z * hv.x;
    }
    {
        float r = sigm(ir.y + hr.y), z = sigm(iz.y + hz.y);
        o.y = (1.f - z) * tanhf(in_.y + r * hn.y) + z * hv.y;
    }
    {
        float r = sigm(ir.z + hr.z), z = sigm(iz.z + hz.z);
        o.z = (1.f - z) * tanhf(in_.z + r * hn.z) + z * hv.z;
    }
    {
        float r = sigm(ir.w + hr.w), z = sigm(iz.w + hz.w);
        o.w = (1.f - z) * tanhf(in_.w + r * hn.w) + z * hv.w;
    }
    *((float4*)g_h + i) = o;
    if (hout) *((float4*)hout + i) = o;
}

// ---------------- launch ----------------
extern "C" void kernel_launch(void* const* d_in, const int* in_sizes, int n_in,
                              void* d_out, int out_size) {
    const float* x    = (const float*)d_in[0];
    const int*   ei   = (const int*)d_in[1];
    const float* ea   = (const float*)d_in[2];
    const float* W    = (const float*)d_in[3];
    const float* W_ih = (const float*)d_in[4];
    const float* W_hh = (const float*)d_in[5];
    const float* b_ih = (const float*)d_in[6];
    const float* b_hh = (const float*)d_in[7];
    float* out = (float*)d_out;

    // one-time stream/event creation (first call is the uncaptured correctness run)
    static cudaStream_t s2 = nullptr, s3 = nullptr;
    static cudaEvent_t evS, evC, evA[3], evB[3];
    if (!s2) {
        cudaStreamCreateWithFlags(&s2, cudaStreamNonBlocking);
        cudaStreamCreateWithFlags(&s3, cudaStreamNonBlocking);
        cudaEventCreateWithFlags(&evS, cudaEventDisableTiming);
        cudaEventCreateWithFlags(&evC, cudaEventDisableTiming);
        for (int l = 0; l < 3; l++) {
            cudaEventCreateWithFlags(&evA[l], cudaEventDisableTiming);
            cudaEventCreateWithFlags(&evB[l], cudaEventDisableTiming);
        }
    }

    float *ph, *pagg, *pgi, *pgh, *pM;
    cudaGetSymbolAddress((void**)&ph,   g_h);
    cudaGetSymbolAddress((void**)&pagg, g_agg);
    cudaGetSymbolAddress((void**)&pgi,  g_gi);
    cudaGetSymbolAddress((void**)&pgh,  g_gh);
    cudaGetSymbolAddress((void**)&pM,   g_M);

    const int n4 = ND / 4;

    // fork point for side streams
    cudaEventRecord(evS, 0);

    // s3: edge conversion + CSR build (independent of h/weights)
    cudaStreamWaitEvent(s3, evS, 0);
    detect_kernel<<<1, 32, 0, s3>>>((const unsigned int*)ei);
    conv_edges_kernel<<<EE / 256, 256, 0, s3>>>(ei);
    zero_deg_kernel<<<(NN + 255) / 256, 256, 0, s3>>>();
    hist_kernel<<<EE / 256, 256, 0, s3>>>();
    scan_kernel<<<1, 256, 0, s3>>>();
    fill_kernel<<<EE / 256, 256, 0, s3>>>(ea);
    cudaEventRecord(evC, s3);

    // default: h init + combined weights
    copy4_kernel<<<n4 / 256, 256>>>((float4*)ph, (const float4*)x, n4);
    mcomb_kernel<<<dim3(192, 3), 256>>>(W, W_ih);

    // default must see the CSR before first gather
    cudaStreamWaitEvent(0, evC, 0);

    for (int l = 0; l < 3; l++) {
        // h is final on default here (copy4 or previous gru)
        cudaEventRecord(evA[l], 0);

        // s2: gh = h @ W_hh^T + b_hh (independent of gather/gi)
        cudaStreamWaitEvent(s2, evA[l], 0);
        gemm_bt_kernel<<<dim3(MBLK, 3), 256, 0, s2>>>(ph, W_hh, b_hh, pgh, NN, 384);
        cudaEventRecord(evB[l], s2);

        // default: gather -> gi
        gather_kernel<<<(NN * 32 + 255) / 256, 256>>>();
        gemm_bt_kernel<<<dim3(MBLK, 3), 256>>>(pagg, pM + (size_t)l * 384 * 128, b_ih, pgi, NN, 384);

        // join gh, then GRU update (layer 2 also writes d_out)
        cudaStreamWaitEvent(0, evB[l], 0);
        gru_kernel<<<(n4 + 255) / 256, 256>>>(l == 2 ? out : nullptr);
    }
}